// round 4
// baseline (speedup 1.0000x reference)
#include <cuda_runtime.h>
#include <cuda_bf16.h>
#include <stdint.h>

#define TOKENS 16384
#define DIM    256
#define KW     8192
#define KP     768          // packed K (3 x 256)

#define BM     128
#define BN     128
#define BK     64
#define SPLIT  8
#define NRANGE (KW / SPLIT)          // 1024 codes per CTA
#define NCHUNKS (NRANGE / BN)        // 8
#define KSTAGES (KP / BK)            // 12
#define GSTAGES (NCHUNKS * KSTAGES)  // 96

#define ROWB   144                    // smem row stride bytes (72 bf16)
#define TILEB  (128 * ROWB)           // 18432 bytes per tile
#define STAGEB (2 * TILEB)
#define NBUF   3
#define SMEM_BYTES (NBUF * STAGEB)    // 110592

#define MARGIN 0.1f

// ---------------- device scratch ----------------
__device__ float g_wn[KW];
__device__ float g_pval[TOKENS * SPLIT];
__device__ float g_pval2[TOKENS * SPLIT];
__device__ int   g_pidx[TOKENS * SPLIT];
__device__ int   g_flag[TOKENS];
__device__ __nv_bfloat16 g_xp[(size_t)TOKENS * KP];   // [xh | xh | xl]
__device__ __nv_bfloat16 g_wp[(size_t)KW * KP];       // [wh | wl | wh]

// ---------------- helpers ----------------
__device__ __forceinline__ uint32_t smem_u32(const void* p) {
    uint32_t a;
    asm("{ .reg .u64 t; cvta.to.shared.u64 t, %1; cvt.u32.u64 %0, t; }" : "=r"(a) : "l"(p));
    return a;
}

#define CP_ASYNC16(dst, src) \
    asm volatile("cp.async.cg.shared.global [%0], [%1], 16;" :: "r"(dst), "l"(src) : "memory")

#define LDSM_X4(r0, r1, r2, r3, addr) \
    asm volatile("ldmatrix.sync.aligned.m8n8.x4.shared.b16 {%0,%1,%2,%3}, [%4];" \
                 : "=r"(r0), "=r"(r1), "=r"(r2), "=r"(r3) : "r"(addr))

#define MMA_BF16(c, a0, a1, a2, a3, b0, b1) \
    asm volatile("mma.sync.aligned.m16n8k16.row.col.f32.bf16.bf16.f32 " \
                 "{%0,%1,%2,%3}, {%4,%5,%6,%7}, {%8,%9}, {%0,%1,%2,%3};" \
                 : "+f"((c)[0]), "+f"((c)[1]), "+f"((c)[2]), "+f"((c)[3]) \
                 : "r"(a0), "r"(a1), "r"(a2), "r"(a3), "r"(b0), "r"(b1))

// streaming top-2 insert (distinct n per call site)
__device__ __forceinline__ void top2_ins(float s, int n, float& v1, int& i1, float& v2) {
    if (s > v1 || (s == v1 && n < i1)) { v2 = v1; v1 = s; i1 = n; }
    else if (s > v2) v2 = s;
}
// merge another top-2 set (disjoint index ranges)
__device__ __forceinline__ void top2_mrg(float ov1, int oi1, float ov2,
                                         float& v1, int& i1, float& v2) {
    if (ov1 > v1 || (ov1 == v1 && oi1 < i1)) { v2 = fmaxf(v1, ov2); v1 = ov1; i1 = oi1; }
    else v2 = fmaxf(v2, ov1);
}

// ---------------- pre-pass: bf16 hi/lo split into packed K=768 ----------------
__global__ void split_pack_kernel(const float* __restrict__ x, const float* __restrict__ w) {
    const int i = blockIdx.x * 256 + threadIdx.x;
    if (i < TOKENS * DIM) {
        const int t = i >> 8, d = i & 255;
        const float v = x[i];
        const __nv_bfloat16 h = __float2bfloat16(v);
        const __nv_bfloat16 l = __float2bfloat16(v - __bfloat162float(h));
        g_xp[(size_t)t * KP + d]       = h;
        g_xp[(size_t)t * KP + 256 + d] = h;
        g_xp[(size_t)t * KP + 512 + d] = l;
    } else {
        const int j = i - TOKENS * DIM;
        const int t = j >> 8, d = j & 255;
        const float v = w[j];
        const __nv_bfloat16 h = __float2bfloat16(v);
        const __nv_bfloat16 l = __float2bfloat16(v - __bfloat162float(h));
        g_wp[(size_t)t * KP + d]       = h;
        g_wp[(size_t)t * KP + 256 + d] = l;
        g_wp[(size_t)t * KP + 512 + d] = h;
    }
}

__global__ void wnorm_kernel(const float* __restrict__ w) {
    int k = blockIdx.x * 256 + threadIdx.x;
    const float4* row = (const float4*)(w + (size_t)k * DIM);
    float s = 0.f;
#pragma unroll
    for (int i = 0; i < DIM / 4; i++) {
        float4 v = row[i];
        s += v.x * v.x + v.y * v.y + v.z * v.z + v.w * v.w;
    }
    g_wn[k] = s;
}

// ---------------- main kernel ----------------
extern __shared__ char dynsmem[];

__device__ __forceinline__ void prefetch_stage(uint32_t sbase, int gs, int tid,
                                               int mbase, int nbase0) {
    const int buf = gs % NBUF;
    const int chunk = gs / KSTAGES;
    const int kb = (gs % KSTAGES) * BK;
    const int nb = nbase0 + chunk * BN;
    const uint32_t base = sbase + buf * STAGEB;
    const int col = tid & 7;
    const int r0 = tid >> 3;
#pragma unroll
    for (int i = 0; i < 4; i++) {
        const int r = r0 + 32 * i;
        const uint32_t dst = base + r * ROWB + col * 16;
        const __nv_bfloat16* src = g_xp + (size_t)(mbase + r) * KP + kb + col * 8;
        CP_ASYNC16(dst, src);
    }
#pragma unroll
    for (int i = 0; i < 4; i++) {
        const int r = r0 + 32 * i;
        const uint32_t dst = base + TILEB + r * ROWB + col * 16;
        const __nv_bfloat16* src = g_wp + (size_t)(nb + r) * KP + kb + col * 8;
        CP_ASYNC16(dst, src);
    }
    asm volatile("cp.async.commit_group;" ::: "memory");
}

__global__ __launch_bounds__(256, 1)
void vq_mma_kernel() {
    char* sm = dynsmem;
    const uint32_t sbase = smem_u32(sm);
    const int tid = threadIdx.x;
    const int lane = tid & 31;
    const int wid = tid >> 5;
    const int warp_m = wid >> 2;
    const int warp_n = wid & 3;
    const int mbase = blockIdx.x * BM;
    const int nbase0 = blockIdx.y * NRANGE;

    const uint32_t aOff = (uint32_t)(warp_m * 64 + ((lane >> 3) & 1) * 8 + (lane & 7)) * ROWB
                        + ((lane >> 4) & 1) * 16;
    const uint32_t bOff = (uint32_t)(warp_n * 32 + ((lane >> 4) & 1) * 8 + (lane & 7)) * ROWB
                        + ((lane >> 3) & 1) * 16;

    float acc[4][4][4];
#pragma unroll
    for (int f = 0; f < 4; f++)
#pragma unroll
        for (int j = 0; j < 4; j++)
#pragma unroll
            for (int e = 0; e < 4; e++) acc[f][j][e] = 0.f;

    float bv[8], bv2[8];
    int   bi[8];
#pragma unroll
    for (int s = 0; s < 8; s++) { bv[s] = -3.402823e38f; bv2[s] = -3.402823e38f; bi[s] = 0x7fffffff; }

    prefetch_stage(sbase, 0, tid, mbase, nbase0);
    prefetch_stage(sbase, 1, tid, mbase, nbase0);

    for (int gs = 0; gs < GSTAGES; gs++) {
        if (gs + 1 < GSTAGES)
            asm volatile("cp.async.wait_group 1;" ::: "memory");
        else
            asm volatile("cp.async.wait_group 0;" ::: "memory");
        __syncthreads();

        if (gs + 2 < GSTAGES)
            prefetch_stage(sbase, gs + 2, tid, mbase, nbase0);

        const int buf = gs % NBUF;
        const uint32_t abase = sbase + buf * STAGEB;
        const uint32_t bbase = abase + TILEB;

#pragma unroll
        for (int k = 0; k < BK / 16; k++) {
            uint32_t a[4][4];
#pragma unroll
            for (int f = 0; f < 4; f++)
                LDSM_X4(a[f][0], a[f][1], a[f][2], a[f][3],
                        abase + aOff + f * 16 * ROWB + k * 32);
            uint32_t b[8];
            LDSM_X4(b[0], b[1], b[2], b[3], bbase + bOff + k * 32);
            LDSM_X4(b[4], b[5], b[6], b[7], bbase + bOff + 16 * ROWB + k * 32);
#pragma unroll
            for (int f = 0; f < 4; f++)
#pragma unroll
                for (int j = 0; j < 4; j++)
                    MMA_BF16(acc[f][j], a[f][0], a[f][1], a[f][2], a[f][3],
                             b[2 * j], b[2 * j + 1]);
        }

        if ((gs % KSTAGES) == KSTAGES - 1) {
            const int chunk = gs / KSTAGES;
            const int nb = nbase0 + chunk * BN;
#pragma unroll
            for (int f = 0; f < 4; f++) {
#pragma unroll
                for (int j = 0; j < 4; j++) {
                    const int n0 = nb + warp_n * 32 + j * 8 + (lane & 3) * 2;
                    const float wn0 = __ldg(&g_wn[n0]);
                    const float wn1 = __ldg(&g_wn[n0 + 1]);
                    const float s00 = wn0 - 2.f * acc[f][j][0];
                    const float s01 = wn1 - 2.f * acc[f][j][1];
                    const float s10 = wn0 - 2.f * acc[f][j][2];
                    const float s11 = wn1 - 2.f * acc[f][j][3];
                    const int t0 = 2 * f, t1 = 2 * f + 1;
                    top2_ins(s00, n0,     bv[t0], bi[t0], bv2[t0]);
                    top2_ins(s01, n0 + 1, bv[t0], bi[t0], bv2[t0]);
                    top2_ins(s10, n0,     bv[t1], bi[t1], bv2[t1]);
                    top2_ins(s11, n0 + 1, bv[t1], bi[t1], bv2[t1]);
                    acc[f][j][0] = 0.f; acc[f][j][1] = 0.f;
                    acc[f][j][2] = 0.f; acc[f][j][3] = 0.f;
                }
            }
        }
    }

    // cross-lane top-2 reduce (lanes sharing rows differ in bits 0-1)
#pragma unroll
    for (int off = 1; off <= 2; off <<= 1) {
#pragma unroll
        for (int s = 0; s < 8; s++) {
            float ov1 = __shfl_xor_sync(0xffffffffu, bv[s], off);
            int   oi1 = __shfl_xor_sync(0xffffffffu, bi[s], off);
            float ov2 = __shfl_xor_sync(0xffffffffu, bv2[s], off);
            top2_mrg(ov1, oi1, ov2, bv[s], bi[s], bv2[s]);
        }
    }

    __syncthreads();
    float* red_val  = (float*)sm;
    int*   red_idx  = (int*)(sm + 2048);
    float* red_val2 = (float*)(sm + 4096);

    if ((lane & 3) == 0) {
        const int g = lane >> 2;
#pragma unroll
        for (int s = 0; s < 8; s++) {
            const int row = warp_m * 64 + (s >> 1) * 16 + (s & 1) * 8 + g;
            red_val[row * 4 + warp_n]  = bv[s];
            red_idx[row * 4 + warp_n]  = bi[s];
            red_val2[row * 4 + warp_n] = bv2[s];
        }
    }
    __syncthreads();

    if (tid < BM) {
        float v1 = -3.402823e38f, v2 = -3.402823e38f;
        int   i1 = 0x7fffffff;
#pragma unroll
        for (int wn = 0; wn < 4; wn++)
            top2_mrg(red_val[tid * 4 + wn], red_idx[tid * 4 + wn],
                     red_val2[tid * 4 + wn], v1, i1, v2);
        const int tok = mbase + tid;
        g_pval[tok * SPLIT + blockIdx.y]  = v1;
        g_pidx[tok * SPLIT + blockIdx.y]  = i1;
        g_pval2[tok * SPLIT + blockIdx.y] = v2;
    }
}

// ---------------- combine split partials + flag + gather ----------------
__global__ void reduce_gather_kernel(const float* __restrict__ wt, float* __restrict__ out) {
    const int tok = blockIdx.x;
    float v1 = -3.402823e38f, v2 = -3.402823e38f;
    int   i1 = 0x7fffffff;
#pragma unroll
    for (int s = 0; s < SPLIT; s++)
        top2_mrg(g_pval[tok * SPLIT + s], g_pidx[tok * SPLIT + s],
                 g_pval2[tok * SPLIT + s], v1, i1, v2);
    const int flag = (v1 - v2 < MARGIN) ? 1 : 0;
    if (threadIdx.x == 0) g_flag[tok] = flag;
    if (!flag) {
        const float4 v = *(const float4*)(wt + (size_t)i1 * DIM + threadIdx.x * 4);
        *(float4*)(out + (size_t)tok * DIM + threadIdx.x * 4) = v;
    }
}

// ---------------- exact fp32 rescue for flagged tokens ----------------
__global__ __launch_bounds__(256)
void rescue_kernel(const float* __restrict__ x, const float* __restrict__ wt,
                   float* __restrict__ out) {
    const int tok = blockIdx.x;
    if (!g_flag[tok]) return;

    __shared__ float xs[DIM];
    __shared__ float rv[8];
    __shared__ int   ri[8];
    __shared__ int   widx;

    const int tid = threadIdx.x;
    if (tid < DIM / 4)
        *(float4*)(xs + tid * 4) = *(const float4*)(x + (size_t)tok * DIM + tid * 4);
    __syncthreads();

    float bv = -3.402823e38f;
    int   bi = 0x7fffffff;
    for (int n = tid; n < KW; n += 256) {
        const float* wr = wt + (size_t)n * DIM;
        float d = 0.f;
#pragma unroll
        for (int c = 0; c < DIM / 4; c++) {
            const float4 wv = __ldg((const float4*)(wr + c * 4));
            const float4 xv = *(const float4*)(xs + c * 4);
            d += xv.x * wv.x + xv.y * wv.y + xv.z * wv.z + xv.w * wv.w;
        }
        const float sc = __ldg(&g_wn[n]) - 2.f * d;
        if (sc > bv || (sc == bv && n < bi)) { bv = sc; bi = n; }
    }
#pragma unroll
    for (int off = 16; off >= 1; off >>= 1) {
        float ov = __shfl_xor_sync(0xffffffffu, bv, off);
        int   oi = __shfl_xor_sync(0xffffffffu, bi, off);
        if (ov > bv || (ov == bv && oi < bi)) { bv = ov; bi = oi; }
    }
    if ((tid & 31) == 0) { rv[tid >> 5] = bv; ri[tid >> 5] = bi; }
    __syncthreads();
    if (tid == 0) {
        float v = rv[0]; int i = ri[0];
#pragma unroll
        for (int wgi = 1; wgi < 8; wgi++) {
            if (rv[wgi] > v || (rv[wgi] == v && ri[wgi] < i)) { v = rv[wgi]; i = ri[wgi]; }
        }
        widx = i;
    }
    __syncthreads();
    const int sel = widx;
    if (tid < DIM / 4) {
        const float4 v = *(const float4*)(wt + (size_t)sel * DIM + tid * 4);
        *(float4*)(out + (size_t)tok * DIM + tid * 4) = v;
    }
}

// ---------------- launch ----------------
extern "C" void kernel_launch(void* const* d_in, const int* in_sizes, int n_in,
                              void* d_out, int out_size) {
    const float* x  = (const float*)d_in[0];   // [16384, 256]
    const float* wt = (const float*)d_in[1];   // [8192, 256]
    float* out = (float*)d_out;

    cudaFuncSetAttribute(vq_mma_kernel, cudaFuncAttributeMaxDynamicSharedMemorySize, SMEM_BYTES);

    split_pack_kernel<<<(TOKENS + KW) * DIM / 256, 256>>>(x, wt);
    wnorm_kernel<<<KW / 256, 256>>>(wt);

    dim3 grid(TOKENS / BM, SPLIT);
    vq_mma_kernel<<<grid, 256, SMEM_BYTES>>>();

    reduce_gather_kernel<<<TOKENS, 64>>>(wt, out);
    rescue_kernel<<<TOKENS, 256>>>(x, wt, out);
}

// round 5
// speedup vs baseline: 1.3672x; 1.3672x over previous
#include <cuda_runtime.h>
#include <cuda_fp16.h>
#include <stdint.h>

#define TOKENS 16384
#define DIM    256
#define KW     8192

#define BM     128
#define BN     128
#define BK     64
#define SPLIT  8
#define NRANGE (KW / SPLIT)          // 1024 codes per CTA
#define NCHUNKS (NRANGE / BN)        // 8
#define KSTAGES (DIM / BK)           // 4
#define GSTAGES (NCHUNKS * KSTAGES)  // 32

#define ROWB   144                    // smem row stride bytes (72 halves)
#define TILEB  (128 * ROWB)           // 18432 bytes per tile
#define STAGEB (2 * TILEB)
#define NBUF   3
#define SMEM_BYTES (NBUF * STAGEB)    // 110592

#define MARGIN 0.1f

// ---------------- device scratch ----------------
__device__ float g_wn[KW];
__device__ float g_pval[TOKENS * SPLIT];
__device__ float g_pval2[TOKENS * SPLIT];
__device__ int   g_pidx[TOKENS * SPLIT];
__device__ int   g_flag[TOKENS];
__device__ __half g_xh[(size_t)TOKENS * DIM];
__device__ __half g_wh[(size_t)KW * DIM];

// ---------------- helpers ----------------
__device__ __forceinline__ uint32_t smem_u32(const void* p) {
    uint32_t a;
    asm("{ .reg .u64 t; cvta.to.shared.u64 t, %1; cvt.u32.u64 %0, t; }" : "=r"(a) : "l"(p));
    return a;
}

#define CP_ASYNC16(dst, src) \
    asm volatile("cp.async.cg.shared.global [%0], [%1], 16;" :: "r"(dst), "l"(src) : "memory")

#define LDSM_X4(r0, r1, r2, r3, addr) \
    asm volatile("ldmatrix.sync.aligned.m8n8.x4.shared.b16 {%0,%1,%2,%3}, [%4];" \
                 : "=r"(r0), "=r"(r1), "=r"(r2), "=r"(r3) : "r"(addr))

#define MMA_F16(c, a0, a1, a2, a3, b0, b1) \
    asm volatile("mma.sync.aligned.m16n8k16.row.col.f32.f16.f16.f32 " \
                 "{%0,%1,%2,%3}, {%4,%5,%6,%7}, {%8,%9}, {%0,%1,%2,%3};" \
                 : "+f"((c)[0]), "+f"((c)[1]), "+f"((c)[2]), "+f"((c)[3]) \
                 : "r"(a0), "r"(a1), "r"(a2), "r"(a3), "r"(b0), "r"(b1))

__device__ __forceinline__ void top2_ins(float s, int n, float& v1, int& i1, float& v2) {
    if (s > v1 || (s == v1 && n < i1)) { v2 = v1; v1 = s; i1 = n; }
    else if (s > v2) v2 = s;
}
__device__ __forceinline__ void top2_mrg(float ov1, int oi1, float ov2,
                                         float& v1, int& i1, float& v2) {
    if (ov1 > v1 || (ov1 == v1 && oi1 < i1)) { v2 = fmaxf(v1, ov2); v1 = ov1; i1 = oi1; }
    else v2 = fmaxf(v2, ov1);
}

// ---------------- pre-pass: fp32 -> fp16 convert + w norms ----------------
__global__ void convert_kernel(const float* __restrict__ x, const float* __restrict__ w) {
    const int i = blockIdx.x * 256 + threadIdx.x;   // float4 index
    const int NX = TOKENS * DIM / 4;
    if (i < NX) {
        const float4 v = ((const float4*)x)[i];
        __half2 h0 = __floats2half2_rn(v.x, v.y);
        __half2 h1 = __floats2half2_rn(v.z, v.w);
        ((__half2*)g_xh)[i * 2]     = h0;
        ((__half2*)g_xh)[i * 2 + 1] = h1;
    } else {
        const int j = i - NX;
        const float4 v = ((const float4*)w)[j];
        __half2 h0 = __floats2half2_rn(v.x, v.y);
        __half2 h1 = __floats2half2_rn(v.z, v.w);
        ((__half2*)g_wh)[j * 2]     = h0;
        ((__half2*)g_wh)[j * 2 + 1] = h1;
    }
}

__global__ void wnorm_kernel(const float* __restrict__ w) {
    int k = blockIdx.x * 256 + threadIdx.x;
    const float4* row = (const float4*)(w + (size_t)k * DIM);
    float s = 0.f;
#pragma unroll
    for (int i = 0; i < DIM / 4; i++) {
        float4 v = row[i];
        s += v.x * v.x + v.y * v.y + v.z * v.z + v.w * v.w;
    }
    g_wn[k] = s;
}

// ---------------- main kernel ----------------
extern __shared__ char dynsmem[];

__device__ __forceinline__ void prefetch_stage(uint32_t sbase, int gs, int tid,
                                               int mbase, int nbase0) {
    const int buf = gs % NBUF;
    const int chunk = gs / KSTAGES;
    const int kb = (gs % KSTAGES) * BK;
    const int nb = nbase0 + chunk * BN;
    const uint32_t base = sbase + buf * STAGEB;
    const int col = tid & 7;
    const int r0 = tid >> 3;
#pragma unroll
    for (int i = 0; i < 4; i++) {
        const int r = r0 + 32 * i;
        const uint32_t dst = base + r * ROWB + col * 16;
        const __half* src = g_xh + (size_t)(mbase + r) * DIM + kb + col * 8;
        CP_ASYNC16(dst, src);
    }
#pragma unroll
    for (int i = 0; i < 4; i++) {
        const int r = r0 + 32 * i;
        const uint32_t dst = base + TILEB + r * ROWB + col * 16;
        const __half* src = g_wh + (size_t)(nb + r) * DIM + kb + col * 8;
        CP_ASYNC16(dst, src);
    }
    asm volatile("cp.async.commit_group;" ::: "memory");
}

__global__ __launch_bounds__(256, 1)
void vq_mma_kernel() {
    char* sm = dynsmem;
    const uint32_t sbase = smem_u32(sm);
    const int tid = threadIdx.x;
    const int lane = tid & 31;
    const int wid = tid >> 5;
    const int warp_m = wid >> 2;
    const int warp_n = wid & 3;
    const int mbase = blockIdx.x * BM;
    const int nbase0 = blockIdx.y * NRANGE;

    const uint32_t aOff = (uint32_t)(warp_m * 64 + ((lane >> 3) & 1) * 8 + (lane & 7)) * ROWB
                        + ((lane >> 4) & 1) * 16;
    const uint32_t bOff = (uint32_t)(warp_n * 32 + ((lane >> 4) & 1) * 8 + (lane & 7)) * ROWB
                        + ((lane >> 3) & 1) * 16;

    float acc[4][4][4];
#pragma unroll
    for (int f = 0; f < 4; f++)
#pragma unroll
        for (int j = 0; j < 4; j++)
#pragma unroll
            for (int e = 0; e < 4; e++) acc[f][j][e] = 0.f;

    float bv[8], bv2[8];
    int   bi[8];
#pragma unroll
    for (int s = 0; s < 8; s++) { bv[s] = -3.402823e38f; bv2[s] = -3.402823e38f; bi[s] = 0x7fffffff; }

    prefetch_stage(sbase, 0, tid, mbase, nbase0);
    prefetch_stage(sbase, 1, tid, mbase, nbase0);

    for (int gs = 0; gs < GSTAGES; gs++) {
        if (gs + 1 < GSTAGES)
            asm volatile("cp.async.wait_group 1;" ::: "memory");
        else
            asm volatile("cp.async.wait_group 0;" ::: "memory");
        __syncthreads();

        if (gs + 2 < GSTAGES)
            prefetch_stage(sbase, gs + 2, tid, mbase, nbase0);

        const int buf = gs % NBUF;
        const uint32_t abase = sbase + buf * STAGEB;
        const uint32_t bbase = abase + TILEB;

#pragma unroll
        for (int k = 0; k < BK / 16; k++) {
            uint32_t a[4][4];
#pragma unroll
            for (int f = 0; f < 4; f++)
                LDSM_X4(a[f][0], a[f][1], a[f][2], a[f][3],
                        abase + aOff + f * 16 * ROWB + k * 32);
            uint32_t b[8];
            LDSM_X4(b[0], b[1], b[2], b[3], bbase + bOff + k * 32);
            LDSM_X4(b[4], b[5], b[6], b[7], bbase + bOff + 16 * ROWB + k * 32);
#pragma unroll
            for (int f = 0; f < 4; f++)
#pragma unroll
                for (int j = 0; j < 4; j++)
                    MMA_F16(acc[f][j], a[f][0], a[f][1], a[f][2], a[f][3],
                            b[2 * j], b[2 * j + 1]);
        }

        if ((gs % KSTAGES) == KSTAGES - 1) {
            const int chunk = gs / KSTAGES;
            const int nb = nbase0 + chunk * BN;
#pragma unroll
            for (int f = 0; f < 4; f++) {
#pragma unroll
                for (int j = 0; j < 4; j++) {
                    const int n0 = nb + warp_n * 32 + j * 8 + (lane & 3) * 2;
                    const float wn0 = __ldg(&g_wn[n0]);
                    const float wn1 = __ldg(&g_wn[n0 + 1]);
                    const float s00 = wn0 - 2.f * acc[f][j][0];
                    const float s01 = wn1 - 2.f * acc[f][j][1];
                    const float s10 = wn0 - 2.f * acc[f][j][2];
                    const float s11 = wn1 - 2.f * acc[f][j][3];
                    const int t0 = 2 * f, t1 = 2 * f + 1;
                    top2_ins(s00, n0,     bv[t0], bi[t0], bv2[t0]);
                    top2_ins(s01, n0 + 1, bv[t0], bi[t0], bv2[t0]);
                    top2_ins(s10, n0,     bv[t1], bi[t1], bv2[t1]);
                    top2_ins(s11, n0 + 1, bv[t1], bi[t1], bv2[t1]);
                    acc[f][j][0] = 0.f; acc[f][j][1] = 0.f;
                    acc[f][j][2] = 0.f; acc[f][j][3] = 0.f;
                }
            }
        }
    }

#pragma unroll
    for (int off = 1; off <= 2; off <<= 1) {
#pragma unroll
        for (int s = 0; s < 8; s++) {
            float ov1 = __shfl_xor_sync(0xffffffffu, bv[s], off);
            int   oi1 = __shfl_xor_sync(0xffffffffu, bi[s], off);
            float ov2 = __shfl_xor_sync(0xffffffffu, bv2[s], off);
            top2_mrg(ov1, oi1, ov2, bv[s], bi[s], bv2[s]);
        }
    }

    __syncthreads();
    float* red_val  = (float*)sm;
    int*   red_idx  = (int*)(sm + 2048);
    float* red_val2 = (float*)(sm + 4096);

    if ((lane & 3) == 0) {
        const int g = lane >> 2;
#pragma unroll
        for (int s = 0; s < 8; s++) {
            const int row = warp_m * 64 + (s >> 1) * 16 + (s & 1) * 8 + g;
            red_val[row * 4 + warp_n]  = bv[s];
            red_idx[row * 4 + warp_n]  = bi[s];
            red_val2[row * 4 + warp_n] = bv2[s];
        }
    }
    __syncthreads();

    if (tid < BM) {
        float v1 = -3.402823e38f, v2 = -3.402823e38f;
        int   i1 = 0x7fffffff;
#pragma unroll
        for (int wn = 0; wn < 4; wn++)
            top2_mrg(red_val[tid * 4 + wn], red_idx[tid * 4 + wn],
                     red_val2[tid * 4 + wn], v1, i1, v2);
        const int tok = mbase + tid;
        g_pval[tok * SPLIT + blockIdx.y]  = v1;
        g_pidx[tok * SPLIT + blockIdx.y]  = i1;
        g_pval2[tok * SPLIT + blockIdx.y] = v2;
    }
}

// ---------------- combine split partials + flag + gather ----------------
__global__ void reduce_gather_kernel(const float* __restrict__ wt, float* __restrict__ out) {
    const int tok = blockIdx.x;
    float v1 = -3.402823e38f, v2 = -3.402823e38f;
    int   i1 = 0x7fffffff;
#pragma unroll
    for (int s = 0; s < SPLIT; s++)
        top2_mrg(g_pval[tok * SPLIT + s], g_pidx[tok * SPLIT + s],
                 g_pval2[tok * SPLIT + s], v1, i1, v2);
    const int flag = (v1 - v2 < MARGIN) ? 1 : 0;
    if (threadIdx.x == 0) g_flag[tok] = flag;
    if (!flag) {
        const float4 v = *(const float4*)(wt + (size_t)i1 * DIM + threadIdx.x * 4);
        *(float4*)(out + (size_t)tok * DIM + threadIdx.x * 4) = v;
    }
}

// ---------------- exact fp32 rescue for flagged tokens ----------------
__global__ __launch_bounds__(256)
void rescue_kernel(const float* __restrict__ x, const float* __restrict__ wt,
                   float* __restrict__ out) {
    const int tok = blockIdx.x;
    if (!g_flag[tok]) return;

    __shared__ float xs[DIM];
    __shared__ float rv[8];
    __shared__ int   ri[8];
    __shared__ int   widx;

    const int tid = threadIdx.x;
    if (tid < DIM / 4)
        *(float4*)(xs + tid * 4) = *(const float4*)(x + (size_t)tok * DIM + tid * 4);
    __syncthreads();

    float bv = -3.402823e38f;
    int   bi = 0x7fffffff;
    for (int n = tid; n < KW; n += 256) {
        const float* wr = wt + (size_t)n * DIM;
        float d = 0.f;
#pragma unroll
        for (int c = 0; c < DIM / 4; c++) {
            const float4 wv = __ldg((const float4*)(wr + c * 4));
            const float4 xv = *(const float4*)(xs + c * 4);
            d += xv.x * wv.x + xv.y * wv.y + xv.z * wv.z + xv.w * wv.w;
        }
        const float sc = __ldg(&g_wn[n]) - 2.f * d;
        if (sc > bv || (sc == bv && n < bi)) { bv = sc; bi = n; }
    }
#pragma unroll
    for (int off = 16; off >= 1; off >>= 1) {
        float ov = __shfl_xor_sync(0xffffffffu, bv, off);
        int   oi = __shfl_xor_sync(0xffffffffu, bi, off);
        if (ov > bv || (ov == bv && oi < bi)) { bv = ov; bi = oi; }
    }
    if ((tid & 31) == 0) { rv[tid >> 5] = bv; ri[tid >> 5] = bi; }
    __syncthreads();
    if (tid == 0) {
        float v = rv[0]; int i = ri[0];
#pragma unroll
        for (int wgi = 1; wgi < 8; wgi++) {
            if (rv[wgi] > v || (rv[wgi] == v && ri[wgi] < i)) { v = rv[wgi]; i = ri[wgi]; }
        }
        widx = i;
    }
    __syncthreads();
    const int sel = widx;
    if (tid < DIM / 4) {
        const float4 v = *(const float4*)(wt + (size_t)sel * DIM + tid * 4);
        *(float4*)(out + (size_t)tok * DIM + tid * 4) = v;
    }
}

// ---------------- launch ----------------
extern "C" void kernel_launch(void* const* d_in, const int* in_sizes, int n_in,
                              void* d_out, int out_size) {
    const float* x  = (const float*)d_in[0];   // [16384, 256]
    const float* wt = (const float*)d_in[1];   // [8192, 256]
    float* out = (float*)d_out;

    cudaFuncSetAttribute(vq_mma_kernel, cudaFuncAttributeMaxDynamicSharedMemorySize, SMEM_BYTES);

    convert_kernel<<<(TOKENS + KW) * DIM / 4 / 256, 256>>>(x, wt);
    wnorm_kernel<<<KW / 256, 256>>>(wt);

    dim3 grid(TOKENS / BM, SPLIT);
    vq_mma_kernel<<<grid, 256, SMEM_BYTES>>>();

    reduce_gather_kernel<<<TOKENS, 64>>>(wt, out);
    rescue_kernel<<<TOKENS, 256>>>(x, wt, out);
}